// round 15
// baseline (speedup 1.0000x reference)
#include <cuda_runtime.h>
#include <cstdint>

#define BATCH 16
#define SEQ   2048
#define DIM   512
#define BD    64
#define NTOK  (BATCH*SEQ)
#define NKVQ  192
#define NTICK (SEQ/4)       /* 512 */

// ---------------- device scratch ----------------
__device__ float g_Wc[DIM*NKVQ];
__device__ float g_bc[NKVQ];
__device__ float g_KVQ[(size_t)NTOK*NKVQ];       // per-token k,v,q
__device__ float g_E[NTOK];
__device__ float g_SC[(size_t)NTOK*12];          // {eta,d1,d2,d3}{d4,d5,d6,d7}{Ea,0,0,0}
__device__ float g_H[(size_t)NTOK*BD];

// ---------------- pack ----------------
__global__ void pack_kernel(const float* __restrict__ Wk, const float* __restrict__ Wv,
                            const float* __restrict__ Wq, const float* __restrict__ bk,
                            const float* __restrict__ bv, const float* __restrict__ bq)
{
    int idx = blockIdx.x*256 + threadIdx.x;
    if (idx < DIM*NKVQ){
        int k = idx / NKVQ, n = idx % NKVQ;
        float v;
        if (n < 64)       v = Wk[k*64 + n];
        else if (n < 128) v = Wv[k*64 + (n-64)];
        else              v = Wq[k*64 + (n-128)];
        g_Wc[idx] = v;
    }
    if (idx < NKVQ){
        float v;
        if (idx < 64)       v = bk[idx];
        else if (idx < 128) v = bv[idx-64];
        else                v = bq[idx-128];
        g_bc[idx] = v;
    }
}

// ---------------- fp32 GEMM ----------------
template<int KITERS>
__device__ __forceinline__ void gemm_body(
    const float* __restrict__ A, int lda,
    const float* __restrict__ B, int ldb,
    const float* __restrict__ bias,
    float* __restrict__ C, int ldc)
{
    __shared__ __align__(16) float As[16][128];
    __shared__ __align__(16) float Bs[16][64];

    const int tid = threadIdx.x;
    const int tx  = tid & 7;
    const int ty  = tid >> 3;
    const int mBase = blockIdx.x * 128;
    const int nBase = blockIdx.y * 64;

    const float* Ab = A + (size_t)mBase * lda;
    const float* Bb = B + nBase;

    float acc[8][8];
    #pragma unroll
    for (int i=0;i<8;i++)
        #pragma unroll
        for (int j=0;j<8;j++) acc[i][j] = 0.f;

    const int am  = tid >> 2;
    const int ak4 = tid & 3;

    for (int kt=0; kt<KITERS; kt++){
        const float* Ak = Ab + kt*16;
        const float* Bk = Bb + (size_t)kt*16*ldb;
        #pragma unroll
        for (int p=0;p<4;p++){
            int m = am + 32*p;
            float4 a = *(const float4*)(Ak + (size_t)m*lda + ak4*4);
            As[ak4*4+0][m]=a.x; As[ak4*4+1][m]=a.y; As[ak4*4+2][m]=a.z; As[ak4*4+3][m]=a.w;
        }
        #pragma unroll
        for (int p=0;p<2;p++){
            int id = tid + 128*p;
            int r = id >> 4, c4 = id & 15;
            *(float4*)(&Bs[r][c4*4]) = *(const float4*)(Bk + (size_t)r*ldb + c4*4);
        }
        __syncthreads();
        #pragma unroll
        for (int kk=0; kk<16; kk++){
            float4 a0 = *(const float4*)(&As[kk][ty*8]);
            float4 a1 = *(const float4*)(&As[kk][ty*8+4]);
            float4 b0 = *(const float4*)(&Bs[kk][tx*8]);
            float4 b1 = *(const float4*)(&Bs[kk][tx*8+4]);
            float av[8] = {a0.x,a0.y,a0.z,a0.w,a1.x,a1.y,a1.z,a1.w};
            float bw[8] = {b0.x,b0.y,b0.z,b0.w,b1.x,b1.y,b1.z,b1.w};
            #pragma unroll
            for (int i=0;i<8;i++)
                #pragma unroll
                for (int j=0;j<8;j++)
                    acc[i][j] = fmaf(av[i], bw[j], acc[i][j]);
        }
        __syncthreads();
    }

    float bvc[8];
    #pragma unroll
    for (int j=0;j<8;j++) bvc[j] = bias[nBase + tx*8 + j];
    #pragma unroll
    for (int i=0;i<8;i++){
        int row = mBase + ty*8 + i;
        float4 o0 = make_float4(acc[i][0]+bvc[0], acc[i][1]+bvc[1],
                                acc[i][2]+bvc[2], acc[i][3]+bvc[3]);
        float4 o1 = make_float4(acc[i][4]+bvc[4], acc[i][5]+bvc[5],
                                acc[i][6]+bvc[6], acc[i][7]+bvc[7]);
        *(float4*)(C + (size_t)row*ldc + nBase + tx*8)     = o0;
        *(float4*)(C + (size_t)row*ldc + nBase + tx*8 + 4) = o1;
    }
}

__global__ void __launch_bounds__(128) gemm1_kernel(const float* __restrict__ x){
    gemm_body<32>(x, DIM, g_Wc, NKVQ, g_bc, g_KVQ, NKVQ);
}
__global__ void __launch_bounds__(128) gemm3_kernel(const float* __restrict__ Wo,
                                                    const float* __restrict__ bo,
                                                    float* __restrict__ out){
    gemm_body<4>(g_H, BD, Wo, DIM, bo, out, DIM);
}

// ---------------- eta ----------------
__global__ void eta_kernel(const float* __restrict__ x,
                           const float* __restrict__ lrw,
                           const float* __restrict__ lrb)
{
    int warp = threadIdx.x >> 5, lane = threadIdx.x & 31;
    int row = blockIdx.x*8 + warp;
    const float* xr = x + (size_t)row*DIM;
    float s = 0.f;
    #pragma unroll
    for (int j=0;j<16;j++) s = fmaf(xr[lane + 32*j], lrw[lane + 32*j], s);
    #pragma unroll
    for (int d=16; d; d>>=1) s += __shfl_xor_sync(0xffffffffu, s, d);
    if (lane == 0){
        float raw = s + lrb[0];
        g_E[row] = 1.f/(1.f + expf(-raw));
    }
}

// ---------------- prep: per-token {eta, d1..d7, Ea} ----------------
__global__ void prep_kernel(const float* __restrict__ lng, const float* __restrict__ lnb)
{
    int warp = threadIdx.x >> 5, lane = threadIdx.x & 31;
    int tok = blockIdx.x*8 + warp;
    int t = tok & (SEQ-1);
    const float* base = g_KVQ + (size_t)tok*192;
    float k0=base[lane],     k1=base[lane+32];
    float v0=base[64+lane],  v1=base[96+lane];
    float g0=lng[lane], g1=lng[lane+32];
    float b0=lnb[lane], b1=lnb[lane+32];
    const float s2 = 2.f/64.f, inv = 1.f/64.f;
    float a0=s2*g0*(k0+b0-v0), a1=s2*g1*(k1+b1-v1);
    float d[7];
    #pragma unroll
    for (int lg=1; lg<=7; lg++){
        float ka=0.f, kb=0.f;
        if (t >= lg){ ka = base[lane - lg*192]; kb = base[lane+32 - lg*192]; }
        d[lg-1] = ka*k0 + kb*k1;
    }
    float ea = a0+a1;
    #pragma unroll
    for (int dd=16; dd; dd>>=1){
        #pragma unroll
        for (int j=0;j<7;j++) d[j] += __shfl_xor_sync(0xffffffffu, d[j], dd);
        ea += __shfl_xor_sync(0xffffffffu, ea, dd);
    }
    if (lane == 0){
        float* sc = g_SC + (size_t)tok*12;
        *(float4*)(sc)   = make_float4(g_E[tok], d[0], d[1], d[2]);
        *(float4*)(sc+4) = make_float4(d[3], d[4], d[5], d[6]);
        *(float4*)(sc+8) = make_float4(ea*inv, 0.f, 0.f, 0.f);
    }
}

// helper matvec over 16 owned cols (4-way partials + pair shfl)
__device__ __forceinline__ float mv16(const float* __restrict__ v, const float* w){
    float4 x0 = *(const float4*)(v);
    float4 x1 = *(const float4*)(v+4);
    float4 x2 = *(const float4*)(v+8);
    float4 x3 = *(const float4*)(v+12);
    float sA = fmaf(w[0],x0.x, w[1]*x0.y);
    float sB = fmaf(w[2],x0.z, w[3]*x0.w);
    float sC = fmaf(w[4],x1.x, w[5]*x1.y);
    float sD = fmaf(w[6],x1.z, w[7]*x1.w);
    sA = fmaf(w[8], x2.x, sA); sA = fmaf(w[9], x2.y, sA);
    sB = fmaf(w[10],x2.z, sB); sB = fmaf(w[11],x2.w, sB);
    sC = fmaf(w[12],x3.x, sC); sC = fmaf(w[13],x3.y, sC);
    sD = fmaf(w[14],x3.z, sD); sD = fmaf(w[15],x3.w, sD);
    float s = (sA+sB)+(sC+sD);
    s += __shfl_xor_sync(0xffffffffu, s, 1);
    s += __shfl_xor_sync(0xffffffffu, s, 2);
    return s;
}

// ---------------- 4-token-per-tick scan, chain warp on a PRIVATE SMSP ----------
// 640 threads = 20 warps. wid%4==3 warps (except wid 3) exit after init barrier,
// so SMSP 3 runs ONLY the chain warp (wid 3) -> its serial dependency chain
// issues at pure latency, no round-robin arbitration.
// Roles: helpers (8) = wids {0,1,2,4,5,6,8,9}; stager = wid 10;
//        LN j=0..3 = wids {12,13,14,16}; chain = wid 3;
//        exit = wids {7,11,15,17,18,19}.
__global__ void __launch_bounds__(640, 1) scan_kernel(
    const float* __restrict__ W0,
    const float* __restrict__ ln_g,
    const float* __restrict__ ln_b)
{
    __shared__ __align__(16) float ring[32][192];
    __shared__ __align__(16) float sSC[32][12];
    __shared__ __align__(16) float sP[2][256];    // [par][i*64+o]
    __shared__ __align__(16) float sU2[2][256];
    __shared__ __align__(16) float sDU[2][256];
    __shared__ float sG[64], sB[64];

    const int tid = threadIdx.x;
    const int wid = tid >> 5;
    const int l   = tid & 31;
    const int b   = blockIdx.x;
    const float* kvq = g_KVQ + (size_t)b*SEQ*192;
    const float* scb = g_SC  + (size_t)b*SEQ*12;
    float*     hbase = g_H   + (size_t)b*SEQ*64;
    const float inv = 1.f/64.f, s2c = 2.f/64.f, eps = 1e-6f;

    // role classification
    const bool isChain  = (wid == 3);
    const bool isStager = (wid == 10);
    const bool isLN     = (wid==12)||(wid==13)||(wid==14)||(wid==16);
    const bool isHelper = (wid<10) && !isChain && (wid!=7);
    const bool isSpare  = !(isChain||isStager||isLN||isHelper);
    const int  h   = isHelper ? (wid - (wid>3) - (wid>7)) : 0;   // 0..7
    const int  lnj = isLN ? ((wid<16)? wid-12 : 3) : 0;           // 0..3

    if (tid < 64){ sG[tid]=ln_g[tid]; sB[tid]=ln_b[tid]; }
    // stage tokens 0..11 (all 640 threads)
    if (tid < 12*48){
        int j = tid/48, i2 = tid%48;
        *(float4*)&ring[j][i2*4] = *(const float4*)(kvq + (size_t)j*192 + i2*4);
    }
    if (tid < 36){
        int j = tid/3, c = tid%3;
        *(float4*)&sSC[j][c*4] = *(const float4*)(scb + (size_t)j*12 + c*4);
    }
    __syncthreads();
    if (isSpare) return;   // retire spare warps; SMSP 3 keeps only the chain warp

    const int o = h*8 + (l>>2), qd = l&3, base = qd*16;  // helper mapping

    float w[16];
    float g0=0,g1=0,bb0=0,bb1=0,G0=0,G1=0,EG=0;
    float2 duH[8]; float etaH[8];
    #pragma unroll
    for (int i=0;i<8;i++){ duH[i]=make_float2(0.f,0.f); etaH[i]=0.f; }
    float4 preA[4], preB[4];
    #pragma unroll
    for (int i=0;i<4;i++){ preA[i]=make_float4(0,0,0,0); preB[i]=make_float4(0,0,0,0); }

    if (isHelper){
        #pragma unroll
        for (int i=0;i<16;i++) w[i] = W0[o*64 + base + i];
        // p~ for tokens 0..3
        #pragma unroll
        for (int i=0;i<4;i++){
            float s = mv16(&ring[i][base], w);
            if (qd==0) sP[0][i*64 + o] = s;
        }
    } else if (isLN){
        g0=sG[2*l]; g1=sG[2*l+1]; bb0=sB[2*l]; bb1=sB[2*l+1];
    } else if (isStager){
        // prefetch tokens 12..15 (stored at tick 0)
        #pragma unroll
        for (int j=0;j<4;j++){
            int s = 12+j;
            preA[j] = *(const float4*)(kvq + (size_t)s*192 + l*4);
            if (l < 16)      preB[j] = *(const float4*)(kvq + (size_t)s*192 + (32+l)*4);
            else if (l < 19) preB[j] = *(const float4*)(scb + (size_t)s*12 + (l-16)*4);
        }
    } else {
        // chain
        g0=sG[2*l]; g1=sG[2*l+1]; bb0=sB[2*l]; bb1=sB[2*l+1];
        G0=s2c*g0*g0; G1=s2c*g1*g1;
        #pragma unroll 8
        for (int j=0;j<64;j++){ float gj=sG[j]; EG += s2c*gj*gj; }
        EG *= inv;
    }
    __syncthreads();

    for (int tau=0; tau<NTICK+2; tau++){
        if (isHelper){
            // updates + exact y for tokens 4tau-4..4tau-1
            if (tau >= 1 && tau <= NTICK){
                #pragma unroll
                for (int i=0;i<4;i++){
                    int slot = (4*tau-4+i) & 31;
                    float coef = sSC[slot][0] * sDU[(tau-1)&1][i*64 + o];
                    const float* kp = &ring[slot][base];
                    #pragma unroll
                    for (int j=0;j<16;j+=4){
                        float4 kk = *(const float4*)(kp+j);
                        w[j]   = fmaf(-coef, kk.x, w[j]);
                        w[j+1] = fmaf(-coef, kk.y, w[j+1]);
                        w[j+2] = fmaf(-coef, kk.z, w[j+2]);
                        w[j+3] = fmaf(-coef, kk.w, w[j+3]);
                    }
                    float y = mv16(&ring[slot][128+base], w);
                    if (qd==0) sU2[tau&1][i*64 + o] = y;
                }
            }
            // p~ for tokens 4tau+4..4tau+7 (next tick)
            if (tau+1 < NTICK){
                #pragma unroll
                for (int i=0;i<4;i++){
                    int slot = (4*tau+4+i) & 31;
                    float s = mv16(&ring[slot][base], w);
                    if (qd==0) sP[(tau+1)&1][i*64 + o] = s;
                }
            }
        } else if (isLN){
            // output LN: token 4(tau-2)+lnj
            if (tau >= 2){
                int tt = 4*(tau-2) + lnj;
                float2 yy = *(const float2*)&sU2[(tau-1)&1][lnj*64 + 2*l];
                float r0 = yy.x+yy.y;
                float r1 = fmaf(yy.x,yy.x, yy.y*yy.y);
                #pragma unroll
                for (int d=16; d; d>>=1){
                    r0 += __shfl_xor_sync(0xffffffffu, r0, d);
                    r1 += __shfl_xor_sync(0xffffffffu, r1, d);
                }
                float mean = r0*inv;
                float vv   = r1*inv - mean*mean;
                float rs   = rsqrtf(vv + eps);
                float2 qq = *(const float2*)&ring[tt&31][128+2*l];
                float h0 = qq.x + (yy.x-mean)*rs*g0 + bb0;
                float h1 = qq.y + (yy.y-mean)*rs*g1 + bb1;
                *(float2*)&hbase[(size_t)tt*64 + 2*l] = make_float2(h0,h1);
            }
        } else if (isStager){
            // STS tokens 4tau+12..15 (prefetched last tick), prefetch 4tau+16..19
            #pragma unroll
            for (int j=0;j<4;j++){
                int s = 4*tau+12+j;
                if (s < SEQ){
                    int slot = s & 31;
                    *(float4*)&ring[slot][l*4] = preA[j];
                    if (l < 16)      *(float4*)&ring[slot][(32+l)*4] = preB[j];
                    else if (l < 19) *(float4*)&sSC[slot][(l-16)*4] = preB[j];
                }
            }
            #pragma unroll
            for (int j=0;j<4;j++){
                int s = 4*tau+16+j;
                if (s < SEQ){
                    preA[j] = *(const float4*)(kvq + (size_t)s*192 + l*4);
                    if (l < 16)      preB[j] = *(const float4*)(kvq + (size_t)s*192 + (32+l)*4);
                    else if (l < 19) preB[j] = *(const float4*)(scb + (size_t)s*12 + (l-16)*4);
                }
            }
        } else {
            // ---- chain warp (wid 3, alone on SMSP 3): tokens 4tau..4tau+3 ----
            if (tau < NTICK){
                float4 sc0[4], sc1[4], sc2[4];
                float2 kk[4], vv[4], pp[4];
                #pragma unroll
                for (int i=0;i<4;i++){
                    int slot = (4*tau+i) & 31;
                    sc0[i] = *(const float4*)&sSC[slot][0];
                    sc1[i] = *(const float4*)&sSC[slot][4];
                    sc2[i] = *(const float4*)&sSC[slot][8];
                    kk[i]  = *(const float2*)&ring[slot][2*l];
                    vv[i]  = *(const float2*)&ring[slot][64+2*l];
                    pp[i]  = *(const float2*)&sP[tau&1][i*64 + 2*l];
                }
                #pragma unroll
                for (int i=0;i<4;i++){
                    float dl[8] = {0.f, sc0[i].y, sc0[i].z, sc0[i].w,
                                   sc1[i].x, sc1[i].y, sc1[i].z, sc1[i].w};
                    float u0 = pp[i].x, u1 = pp[i].y;
                    #pragma unroll
                    for (int lg=1; lg<=4+i; lg++){
                        int j = 4+i-lg;
                        float c = etaH[j]*dl[lg];
                        u0 = fmaf(-c, duH[j].x, u0);
                        u1 = fmaf(-c, duH[j].y, u1);
                    }
                    float a0 = s2c*g0*(kk[i].x+bb0-vv[i].x);
                    float a1 = s2c*g1*(kk[i].y+bb1-vv[i].y);
                    float t0 = G0*u0, t1 = G1*u1;
                    float r0 = u0+u1;
                    float r1 = fmaf(u0,u0, u1*u1);
                    float r2 = t0+t1;
                    float r3 = fmaf(t0,u0, t1*u1);
                    float r4 = fmaf(a0,u0, a1*u1);
                    #pragma unroll
                    for (int d=16; d; d>>=1){
                        r0 += __shfl_xor_sync(0xffffffffu, r0, d);
                        r1 += __shfl_xor_sync(0xffffffffu, r1, d);
                        r2 += __shfl_xor_sync(0xffffffffu, r2, d);
                        r3 += __shfl_xor_sync(0xffffffffu, r3, d);
                        r4 += __shfl_xor_sync(0xffffffffu, r4, d);
                    }
                    float mu   = r0*inv;
                    float var  = r1*inv - mu*mu;
                    float rstd = rsqrtf(var + eps);
                    float rstd2= rstd*rstd;
                    float Ea  = sc2[i].x;
                    float EGu = r2*inv, EGuu = r3*inv, Eau = r4*inv;
                    float m1 = Ea + rstd*(EGu - mu*EG);
                    float m2 = rstd*(Eau - mu*Ea) + rstd2*(EGuu - 2.f*mu*EGu + mu*mu*EG);
                    float hat0 = (u0-mu)*rstd, hat1 = (u1-mu)*rstd;
                    float du0 = rstd*(a0 - m1 + hat0*(G0 - m2));
                    float du1 = rstd*(a1 - m1 + hat1*(G1 - m2));
                    duH[4+i] = make_float2(du0,du1);
                    etaH[4+i] = sc0[i].x;
                    *(float2*)&sDU[tau&1][i*64 + 2*l] = duH[4+i];
                }
                #pragma unroll
                for (int i=0;i<4;i++){ duH[i]=duH[4+i]; etaH[i]=etaH[4+i]; }
            }
        }
        __syncthreads();
    }
}

// ---------------- launch ----------------
extern "C" void kernel_launch(void* const* d_in, const int* in_sizes, int n_in,
                              void* d_out, int out_size)
{
    const float* x   = (const float*)d_in[0];
    const float* Wk  = (const float*)d_in[1];
    const float* bk  = (const float*)d_in[2];
    const float* Wv  = (const float*)d_in[3];
    const float* bv  = (const float*)d_in[4];
    const float* Wq  = (const float*)d_in[5];
    const float* bq  = (const float*)d_in[6];
    const float* Wo  = (const float*)d_in[7];
    const float* bo  = (const float*)d_in[8];
    const float* lng = (const float*)d_in[9];
    const float* lnb = (const float*)d_in[10];
    const float* lrw = (const float*)d_in[11];
    const float* lrb = (const float*)d_in[12];
    const float* W0  = (const float*)d_in[13];
    float* out = (float*)d_out;

    pack_kernel<<<(DIM*NKVQ + 255)/256, 256>>>(Wk, Wv, Wq, bk, bv, bq);
    gemm1_kernel<<<dim3(NTOK/128, 3), 128>>>(x);
    eta_kernel<<<NTOK/8, 256>>>(x, lrw, lrb);
    prep_kernel<<<NTOK/8, 256>>>(lng, lnb);
    scan_kernel<<<BATCH, 640>>>(W0, lng, lnb);
    gemm3_kernel<<<dim3(NTOK/128, 8), 128>>>(Wo, bo, out);
}

// round 16
// speedup vs baseline: 1.2318x; 1.2318x over previous
#include <cuda_runtime.h>
#include <cstdint>

#define BATCH 16
#define SEQ   2048
#define DIM   512
#define BD    64
#define NTOK  (BATCH*SEQ)
#define NKVQ  192
#define NPAIR (SEQ/2)       /* 1024 */

// ---------------- device scratch ----------------
__device__ float g_Wc[DIM*NKVQ];
__device__ float g_bc[NKVQ];
__device__ float g_KVQ[(size_t)NTOK*NKVQ];       // per-token k,v,q
__device__ float g_E[NTOK];
__device__ float g_SC[(size_t)NTOK*8];           // {eta,d1,d2,d3}{Ea,0,0,0}
__device__ float g_H[(size_t)NTOK*BD];

// ---------------- pack ----------------
__global__ void pack_kernel(const float* __restrict__ Wk, const float* __restrict__ Wv,
                            const float* __restrict__ Wq, const float* __restrict__ bk,
                            const float* __restrict__ bv, const float* __restrict__ bq)
{
    int idx = blockIdx.x*256 + threadIdx.x;
    if (idx < DIM*NKVQ){
        int k = idx / NKVQ, n = idx % NKVQ;
        float v;
        if (n < 64)       v = Wk[k*64 + n];
        else if (n < 128) v = Wv[k*64 + (n-64)];
        else              v = Wq[k*64 + (n-128)];
        g_Wc[idx] = v;
    }
    if (idx < NKVQ){
        float v;
        if (idx < 64)       v = bk[idx];
        else if (idx < 128) v = bv[idx-64];
        else                v = bq[idx-128];
        g_bc[idx] = v;
    }
}

// ---------------- fp32 GEMM ----------------
template<int KITERS>
__device__ __forceinline__ void gemm_body(
    const float* __restrict__ A, int lda,
    const float* __restrict__ B, int ldb,
    const float* __restrict__ bias,
    float* __restrict__ C, int ldc)
{
    __shared__ __align__(16) float As[16][128];
    __shared__ __align__(16) float Bs[16][64];

    const int tid = threadIdx.x;
    const int tx  = tid & 7;
    const int ty  = tid >> 3;
    const int mBase = blockIdx.x * 128;
    const int nBase = blockIdx.y * 64;

    const float* Ab = A + (size_t)mBase * lda;
    const float* Bb = B + nBase;

    float acc[8][8];
    #pragma unroll
    for (int i=0;i<8;i++)
        #pragma unroll
        for (int j=0;j<8;j++) acc[i][j] = 0.f;

    const int am  = tid >> 2;
    const int ak4 = tid & 3;

    for (int kt=0; kt<KITERS; kt++){
        const float* Ak = Ab + kt*16;
        const float* Bk = Bb + (size_t)kt*16*ldb;
        #pragma unroll
        for (int p=0;p<4;p++){
            int m = am + 32*p;
            float4 a = *(const float4*)(Ak + (size_t)m*lda + ak4*4);
            As[ak4*4+0][m]=a.x; As[ak4*4+1][m]=a.y; As[ak4*4+2][m]=a.z; As[ak4*4+3][m]=a.w;
        }
        #pragma unroll
        for (int p=0;p<2;p++){
            int id = tid + 128*p;
            int r = id >> 4, c4 = id & 15;
            *(float4*)(&Bs[r][c4*4]) = *(const float4*)(Bk + (size_t)r*ldb + c4*4);
        }
        __syncthreads();
        #pragma unroll
        for (int kk=0; kk<16; kk++){
            float4 a0 = *(const float4*)(&As[kk][ty*8]);
            float4 a1 = *(const float4*)(&As[kk][ty*8+4]);
            float4 b0 = *(const float4*)(&Bs[kk][tx*8]);
            float4 b1 = *(const float4*)(&Bs[kk][tx*8+4]);
            float av[8] = {a0.x,a0.y,a0.z,a0.w,a1.x,a1.y,a1.z,a1.w};
            float bw[8] = {b0.x,b0.y,b0.z,b0.w,b1.x,b1.y,b1.z,b1.w};
            #pragma unroll
            for (int i=0;i<8;i++)
                #pragma unroll
                for (int j=0;j<8;j++)
                    acc[i][j] = fmaf(av[i], bw[j], acc[i][j]);
        }
        __syncthreads();
    }

    float bvc[8];
    #pragma unroll
    for (int j=0;j<8;j++) bvc[j] = bias[nBase + tx*8 + j];
    #pragma unroll
    for (int i=0;i<8;i++){
        int row = mBase + ty*8 + i;
        float4 o0 = make_float4(acc[i][0]+bvc[0], acc[i][1]+bvc[1],
                                acc[i][2]+bvc[2], acc[i][3]+bvc[3]);
        float4 o1 = make_float4(acc[i][4]+bvc[4], acc[i][5]+bvc[5],
                                acc[i][6]+bvc[6], acc[i][7]+bvc[7]);
        *(float4*)(C + (size_t)row*ldc + nBase + tx*8)     = o0;
        *(float4*)(C + (size_t)row*ldc + nBase + tx*8 + 4) = o1;
    }
}

__global__ void __launch_bounds__(128) gemm1_kernel(const float* __restrict__ x){
    gemm_body<32>(x, DIM, g_Wc, NKVQ, g_bc, g_KVQ, NKVQ);
}
__global__ void __launch_bounds__(128) gemm3_kernel(const float* __restrict__ Wo,
                                                    const float* __restrict__ bo,
                                                    float* __restrict__ out){
    gemm_body<4>(g_H, BD, Wo, DIM, bo, out, DIM);
}

// ---------------- eta ----------------
__global__ void eta_kernel(const float* __restrict__ x,
                           const float* __restrict__ lrw,
                           const float* __restrict__ lrb)
{
    int warp = threadIdx.x >> 5, lane = threadIdx.x & 31;
    int row = blockIdx.x*8 + warp;
    const float* xr = x + (size_t)row*DIM;
    float s = 0.f;
    #pragma unroll
    for (int j=0;j<16;j++) s = fmaf(xr[lane + 32*j], lrw[lane + 32*j], s);
    #pragma unroll
    for (int d=16; d; d>>=1) s += __shfl_xor_sync(0xffffffffu, s, d);
    if (lane == 0){
        float raw = s + lrb[0];
        g_E[row] = 1.f/(1.f + expf(-raw));
    }
}

// ---------------- prep: per-token {eta, d1, d2, d3, Ea} ----------------
__global__ void prep_kernel(const float* __restrict__ lng, const float* __restrict__ lnb)
{
    int warp = threadIdx.x >> 5, lane = threadIdx.x & 31;
    int tok = blockIdx.x*8 + warp;
    int t = tok & (SEQ-1);
    const float* base = g_KVQ + (size_t)tok*192;
    float k0=base[lane],     k1=base[lane+32];
    float v0=base[64+lane],  v1=base[96+lane];
    float km1a=0.f,km1b=0.f,km2a=0.f,km2b=0.f,km3a=0.f,km3b=0.f;
    if (t > 0){ km1a = base[lane-192];   km1b = base[lane+32-192]; }
    if (t > 1){ km2a = base[lane-384];   km2b = base[lane+32-384]; }
    if (t > 2){ km3a = base[lane-576];   km3b = base[lane+32-576]; }
    float g0=lng[lane], g1=lng[lane+32];
    float b0=lnb[lane], b1=lnb[lane+32];
    const float s2 = 2.f/64.f, inv = 1.f/64.f;
    float a0=s2*g0*(k0+b0-v0), a1=s2*g1*(k1+b1-v1);
    float r1 = km1a*k0 + km1b*k1;
    float r2 = km2a*k0 + km2b*k1;
    float r3 = km3a*k0 + km3b*k1;
    float r4 = a0+a1;
    #pragma unroll
    for (int d=16; d; d>>=1){
        r1+=__shfl_xor_sync(0xffffffffu,r1,d);
        r2+=__shfl_xor_sync(0xffffffffu,r2,d);
        r3+=__shfl_xor_sync(0xffffffffu,r3,d);
        r4+=__shfl_xor_sync(0xffffffffu,r4,d);
    }
    if (lane == 0){
        float* sc = g_SC + (size_t)tok*8;
        *(float4*)(sc)   = make_float4(g_E[tok], r1, r2, r3);
        *(float4*)(sc+4) = make_float4(r4*inv, 0.f, 0.f, 0.f);
    }
}

// helper matvec over 16 owned cols (4-way partials + pair shfl)
__device__ __forceinline__ float mv16(const float* __restrict__ v, const float* w){
    float4 x0 = *(const float4*)(v);
    float4 x1 = *(const float4*)(v+4);
    float4 x2 = *(const float4*)(v+8);
    float4 x3 = *(const float4*)(v+12);
    float sA = fmaf(w[0],x0.x, w[1]*x0.y);
    float sB = fmaf(w[2],x0.z, w[3]*x0.w);
    float sC = fmaf(w[4],x1.x, w[5]*x1.y);
    float sD = fmaf(w[6],x1.z, w[7]*x1.w);
    sA = fmaf(w[8], x2.x, sA); sA = fmaf(w[9], x2.y, sA);
    sB = fmaf(w[10],x2.z, sB); sB = fmaf(w[11],x2.w, sB);
    sC = fmaf(w[12],x3.x, sC); sC = fmaf(w[13],x3.y, sC);
    sD = fmaf(w[14],x3.z, sD); sD = fmaf(w[15],x3.w, sD);
    float s = (sA+sB)+(sC+sD);
    s += __shfl_xor_sync(0xffffffffu, s, 1);
    s += __shfl_xor_sync(0xffffffffu, s, 2);
    return s;
}

// ---------------- 2-token-per-tick scan, chain warp on PRIVATE SMSP ----------
// 512 threads = 16 warps. Chain = wid 3, ALONE on SMSP 3 (wids 7,11,14,15 exit
// after init), so its serial dependency chain issues at pure latency.
// Working warps on SMSPs 0-2: helpers = wids {0,1,2,4,5,6,8,9} (h=0..7, each
// owns 8 o-rows x 16 cols), stager = wid 10, LN = wids 12 (tok 2tau-4) and
// 13 (tok 2tau-3). Pipeline identical to the proven n=2 design (R10).
__global__ void __launch_bounds__(512, 1) scan_kernel(
    const float* __restrict__ W0,
    const float* __restrict__ ln_g,
    const float* __restrict__ ln_b)
{
    __shared__ __align__(16) float ring[16][192];
    __shared__ __align__(16) float sSC[16][8];
    __shared__ __align__(16) float sP[2][128];   // [pair parity][tok&1 *64 + o]
    __shared__ __align__(16) float sU2[2][128];
    __shared__ __align__(16) float sDU[2][128];
    __shared__ float sG[64], sB[64];

    const int tid = threadIdx.x;
    const int wid = tid >> 5;
    const int l   = tid & 31;
    const int b   = blockIdx.x;
    const float* kvq = g_KVQ + (size_t)b*SEQ*192;
    const float* scb = g_SC  + (size_t)b*SEQ*8;
    float*     hbase = g_H   + (size_t)b*SEQ*64;
    const float inv = 1.f/64.f, s2c = 2.f/64.f, eps = 1e-6f;

    // roles
    const bool isChain  = (wid == 3);
    const bool isStager = (wid == 10);
    const bool isLN0    = (wid == 12);
    const bool isLN1    = (wid == 13);
    const bool isHelper = (wid<10) && (wid!=3) && (wid!=7);
    const bool isSpare  = !(isChain||isStager||isLN0||isLN1||isHelper);
    const int  h = isHelper ? (wid - (wid>3) - (wid>7)) : 0;   // 0..7

    if (tid < 64){ sG[tid]=ln_g[tid]; sB[tid]=ln_b[tid]; }
    // stage tokens 0..7 + sSC 0..7
    if (tid < 384){
        int j = tid/48, i2 = tid%48;
        *(float4*)&ring[j][i2*4] = *(const float4*)(kvq + (size_t)j*192 + i2*4);
    }
    if (tid < 16){
        int j = tid>>1, i2 = tid&1;
        *(float4*)&sSC[j][i2*4] = *(const float4*)(scb + (size_t)j*8 + i2*4);
    }
    __syncthreads();
    if (isSpare) return;   // retire; SMSP 3 keeps only the chain warp

    const int o = h*8 + (l>>2), qd = l&3, base = qd*16;  // helper mapping

    float w[16];
    float g0=0,g1=0,bb0=0,bb1=0,G0=0,G1=0,EG=0;
    float duA0=0,duA1=0,duB0=0,duB1=0, etaA=0, etaB=0;
    float4 preA1,preA2,preB1,preB2;
    preA1=preA2=preB1=preB2 = make_float4(0.f,0.f,0.f,0.f);

    if (isHelper){
        #pragma unroll
        for (int i=0;i<16;i++) w[i] = W0[o*64 + base + i];
        float s0 = mv16(&ring[0][base], w);
        float s1 = mv16(&ring[1][base], w);
        if (qd==0){ sP[0][o] = s0; sP[0][64+o] = s1; }
    } else if (isChain){
        g0=sG[2*l]; g1=sG[2*l+1]; bb0=sB[2*l]; bb1=sB[2*l+1];
        G0=s2c*g0*g0; G1=s2c*g1*g1;
        #pragma unroll 8
        for (int j=0;j<64;j++){ float gj=sG[j]; EG += s2c*gj*gj; }
        EG *= inv;
    } else if (isStager){
        // prefetch tokens 8, 9
        preA1 = *(const float4*)(kvq + (size_t)8*192 + l*4);
        preB1 = *(const float4*)(kvq + (size_t)9*192 + l*4);
        if (l < 16){
            preA2 = *(const float4*)(kvq + (size_t)8*192 + (32+l)*4);
            preB2 = *(const float4*)(kvq + (size_t)9*192 + (32+l)*4);
        } else if (l < 18){
            preA2 = *(const float4*)(scb + (size_t)8*8 + (l-16)*4);
            preB2 = *(const float4*)(scb + (size_t)9*8 + (l-16)*4);
        }
    } else {
        g0=sG[2*l]; g1=sG[2*l+1]; bb0=sB[2*l]; bb1=sB[2*l+1];
    }
    __syncthreads();

    for (int tau=0; tau<=NPAIR+1; tau++){
        if (isHelper){
            // updates + exact y for pair tau-1
            if (tau >= 1 && tau <= NPAIR){
                int tA = 2*tau-2, tB = 2*tau-1;
                const int pr = (tau-1)&1;
                float coefA = sSC[tA&15][0] * sDU[pr][o];
                const float* kA = &ring[tA&15][base];
                #pragma unroll
                for (int i=0;i<16;i+=4){
                    float4 kk = *(const float4*)(kA+i);
                    w[i]   = fmaf(-coefA, kk.x, w[i]);
                    w[i+1] = fmaf(-coefA, kk.y, w[i+1]);
                    w[i+2] = fmaf(-coefA, kk.z, w[i+2]);
                    w[i+3] = fmaf(-coefA, kk.w, w[i+3]);
                }
                float yA = mv16(&ring[tA&15][128+base], w);
                float coefB = sSC[tB&15][0] * sDU[pr][64+o];
                const float* kB = &ring[tB&15][base];
                #pragma unroll
                for (int i=0;i<16;i+=4){
                    float4 kk = *(const float4*)(kB+i);
                    w[i]   = fmaf(-coefB, kk.x, w[i]);
                    w[i+1] = fmaf(-coefB, kk.y, w[i+1]);
                    w[i+2] = fmaf(-coefB, kk.z, w[i+2]);
                    w[i+3] = fmaf(-coefB, kk.w, w[i+3]);
                }
                float yB = mv16(&ring[tB&15][128+base], w);
                if (qd==0){ sU2[tau&1][o] = yA; sU2[tau&1][64+o] = yB; }
            }
            // p~ for pair tau+1
            if (tau < NPAIR){
                int n0 = 2*tau+2, n1 = 2*tau+3;
                float s0 = mv16(&ring[n0&15][base], w);
                float s1 = mv16(&ring[n1&15][base], w);
                if (qd==0){ sP[(tau+1)&1][o] = s0; sP[(tau+1)&1][64+o] = s1; }
            }
        } else if (isChain){
            if (tau < NPAIR){
                const int t0 = 2*tau, t1 = 2*tau+1;
                float2 pp0 = *(const float2*)&sP[tau&1][2*l];
                float2 pp1 = *(const float2*)&sP[tau&1][64+2*l];
                float2 kk0 = *(const float2*)&ring[t0&15][2*l];
                float2 vv0 = *(const float2*)&ring[t0&15][64+2*l];
                float2 kk1 = *(const float2*)&ring[t1&15][2*l];
                float2 vv1 = *(const float2*)&ring[t1&15][64+2*l];
                float4 c0  = *(const float4*)&sSC[t0&15][0];   // eta,d1,d2,d3
                float  Ea0 = sSC[t0&15][4];
                float4 c1  = *(const float4*)&sSC[t1&15][0];
                float  Ea1 = sSC[t1&15][4];

                // ---- token t0 ----
                float ccA = etaA*c0.z, ccB = etaB*c0.y;   // lag2, lag1
                float u0 = pp0.x - ccA*duA0 - ccB*duB0;
                float u1 = pp0.y - ccA*duA1 - ccB*duB1;
                float a0 = s2c*g0*(kk0.x+bb0-vv0.x);
                float a1 = s2c*g1*(kk0.y+bb1-vv0.y);
                float t0a = G0*u0, t1a = G1*u1;
                float r0 = u0+u1;
                float r1 = fmaf(u0,u0, u1*u1);
                float r2 = t0a+t1a;
                float r3 = fmaf(t0a,u0, t1a*u1);
                float r4 = fmaf(a0,u0, a1*u1);
                #pragma unroll
                for (int d=16; d; d>>=1){
                    r0 += __shfl_xor_sync(0xffffffffu, r0, d);
                    r1 += __shfl_xor_sync(0xffffffffu, r1, d);
                    r2 += __shfl_xor_sync(0xffffffffu, r2, d);
                    r3 += __shfl_xor_sync(0xffffffffu, r3, d);
                    r4 += __shfl_xor_sync(0xffffffffu, r4, d);
                }
                float mu   = r0*inv;
                float var  = r1*inv - mu*mu;
                float rstd = rsqrtf(var + eps);
                float rstd2= rstd*rstd;
                float EGu = r2*inv, EGuu = r3*inv, Eau = r4*inv;
                float m1 = Ea0 + rstd*(EGu - mu*EG);
                float m2 = rstd*(Eau - mu*Ea0) + rstd2*(EGuu - 2.f*mu*EGu + mu*mu*EG);
                float hat0 = (u0-mu)*rstd, hat1 = (u1-mu)*rstd;
                float duC0 = rstd*(a0 - m1 + hat0*(G0 - m2));
                float duC1 = rstd*(a1 - m1 + hat1*(G1 - m2));
                float etaC = c0.x;

                // ---- token t1 ----
                float cA = etaA*c1.w, cB = etaB*c1.z, cC = etaC*c1.y; // lag3,2,1
                u0 = pp1.x - cA*duA0 - cB*duB0 - cC*duC0;
                u1 = pp1.y - cA*duA1 - cB*duB1 - cC*duC1;
                a0 = s2c*g0*(kk1.x+bb0-vv1.x);
                a1 = s2c*g1*(kk1.y+bb1-vv1.y);
                t0a = G0*u0; t1a = G1*u1;
                r0 = u0+u1;
                r1 = fmaf(u0,u0, u1*u1);
                r2 = t0a+t1a;
                r3 = fmaf(t0a,u0, t1a*u1);
                r4 = fmaf(a0,u0, a1*u1);
                #pragma unroll
                for (int d=16; d; d>>=1){
                    r0 += __shfl_xor_sync(0xffffffffu, r0, d);
                    r1 += __shfl_xor_sync(0xffffffffu, r1, d);
                    r2 += __shfl_xor_sync(0xffffffffu, r2, d);
                    r3 += __shfl_xor_sync(0xffffffffu, r3, d);
                    r4 += __shfl_xor_sync(0xffffffffu, r4, d);
                }
                mu   = r0*inv;
                var  = r1*inv - mu*mu;
                rstd = rsqrtf(var + eps);
                rstd2= rstd*rstd;
                EGu = r2*inv; EGuu = r3*inv; Eau = r4*inv;
                m1 = Ea1 + rstd*(EGu - mu*EG);
                m2 = rstd*(Eau - mu*Ea1) + rstd2*(EGuu - 2.f*mu*EGu + mu*mu*EG);
                hat0 = (u0-mu)*rstd; hat1 = (u1-mu)*rstd;
                float duD0 = rstd*(a0 - m1 + hat0*(G0 - m2));
                float duD1 = rstd*(a1 - m1 + hat1*(G1 - m2));

                *(float2*)&sDU[tau&1][2*l]    = make_float2(duC0,duC1);
                *(float2*)&sDU[tau&1][64+2*l] = make_float2(duD0,duD1);
                duA0=duC0; duA1=duC1; duB0=duD0; duB1=duD1;
                etaA=etaC; etaB=c1.x;
            }
        } else if (isStager){
            int sA = 2*tau+8, sB2 = 2*tau+9;
            if (sA < SEQ){
                *(float4*)&ring[sA&15][l*4] = preA1;
                if (l < 16)      *(float4*)&ring[sA&15][(32+l)*4] = preA2;
                else if (l < 18) *(float4*)&sSC[sA&15][(l-16)*4] = preA2;
            }
            if (sB2 < SEQ){
                *(float4*)&ring[sB2&15][l*4] = preB1;
                if (l < 16)      *(float4*)&ring[sB2&15][(32+l)*4] = preB2;
                else if (l < 18) *(float4*)&sSC[sB2&15][(l-16)*4] = preB2;
            }
            int pA = 2*tau+10, pB = 2*tau+11;
            if (pA < SEQ){
                preA1 = *(const float4*)(kvq + (size_t)pA*192 + l*4);
                if (l < 16)      preA2 = *(const float4*)(kvq + (size_t)pA*192 + (32+l)*4);
                else if (l < 18) preA2 = *(const float4*)(scb + (size_t)pA*8 + (l-16)*4);
            }
            if (pB < SEQ){
                preB1 = *(const float4*)(kvq + (size_t)pB*192 + l*4);
                if (l < 16)      preB2 = *(const float4*)(kvq + (size_t)pB*192 + (32+l)*4);
                else if (l < 18) preB2 = *(const float4*)(scb + (size_t)pB*8 + (l-16)*4);
            }
        } else {
            // output LN: wid12 -> token 2tau-4, wid13 -> token 2tau-3
            if (tau >= 2){
                int tt = isLN0 ? (2*tau-4) : (2*tau-3);
                int idx = isLN0 ? 2*l : 64+2*l;
                float2 yy = *(const float2*)&sU2[(tau-1)&1][idx];
                float r0 = yy.x+yy.y;
                float r1 = fmaf(yy.x,yy.x, yy.y*yy.y);
                #pragma unroll
                for (int d=16; d; d>>=1){
                    r0 += __shfl_xor_sync(0xffffffffu, r0, d);
                    r1 += __shfl_xor_sync(0xffffffffu, r1, d);
                }
                float mean = r0*inv;
                float vv   = r1*inv - mean*mean;
                float rs   = rsqrtf(vv + eps);
                float2 qq = *(const float2*)&ring[tt&15][128+2*l];
                float h0 = qq.x + (yy.x-mean)*rs*g0 + bb0;
                float h1 = qq.y + (yy.y-mean)*rs*g1 + bb1;
                *(float2*)&hbase[(size_t)tt*64 + 2*l] = make_float2(h0,h1);
            }
        }
        __syncthreads();
    }
}

// ---------------- launch ----------------
extern "C" void kernel_launch(void* const* d_in, const int* in_sizes, int n_in,
                              void* d_out, int out_size)
{
    const float* x   = (const float*)d_in[0];
    const float* Wk  = (const float*)d_in[1];
    const float* bk  = (const float*)d_in[2];
    const float* Wv  = (const float*)d_in[3];
    const float* bv  = (const float*)d_in[4];
    const float* Wq  = (const float*)d_in[5];
    const float* bq  = (const float*)d_in[6];
    const float* Wo  = (const float*)d_in[7];
    const float* bo  = (const float*)d_in[8];
    const float* lng = (const float*)d_in[9];
    const float* lnb = (const float*)d_in[10];
    const float* lrw = (const float*)d_in[11];
    const float* lrb = (const float*)d_in[12];
    const float* W0  = (const float*)d_in[13];
    float* out = (float*)d_out;

    pack_kernel<<<(DIM*NKVQ + 255)/256, 256>>>(Wk, Wv, Wq, bk, bv, bq);
    gemm1_kernel<<<dim3(NTOK/128, 3), 128>>>(x);
    eta_kernel<<<NTOK/8, 256>>>(x, lrw, lrb);
    prep_kernel<<<NTOK/8, 256>>>(lng, lnb);
    scan_kernel<<<BATCH, 512>>>(W0, lng, lnb);
    gemm3_kernel<<<dim3(NTOK/128, 8), 128>>>(Wo, bo, out);
}